// round 13
// baseline (speedup 1.0000x reference)
#include <cuda_runtime.h>
#include <cuda_bf16.h>
#include <cstdint>

#define N_NODES 50000
#define NP      50048          /* padded to 391*128 */
#define N_EDGES 600000
#define IN_C 128
#define HID 128
#define OUT_C 32
#define N_GRAPHS 64

#define SCAN_BS 512
#define SCAN_NB ((N_NODES + SCAN_BS - 1) / SCAN_BS)   // 98

// ---------------- scratch (static device globals) ----------------
__device__ int   g_deg[N_NODES];
__device__ int   g_rowoff[N_NODES + 1];
__device__ int   g_cursor[N_NODES];
__device__ int   g_csr[N_EDGES];
__device__ int   g_pref[SCAN_NB + 1];     // chain prefix
__device__ int   g_ready[SCAN_NB + 1];    // chain flags
__device__ __align__(16) __nv_bfloat16 g_xhi[(size_t)NP * 128], g_xlo[(size_t)NP * 128];
__device__ __align__(16) __nv_bfloat16 g_mhi[(size_t)NP * 128], g_mlo[(size_t)NP * 128];
__device__ __align__(16) __nv_bfloat16 g_h1hi[(size_t)NP * 128], g_h1lo[(size_t)NP * 128];
__device__ __align__(16) __nv_bfloat16 g_whi[4 * 128 * 128], g_wlo[4 * 128 * 128];
__device__ __align__(16) float g_h1[(size_t)NP * 128];
__device__ __align__(16) float g_h2[(size_t)N_NODES * 128];

// ---------------- helpers ----------------
__device__ __forceinline__ uint32_t pack2(__nv_bfloat16 a, __nv_bfloat16 b) {
    uint16_t ua = *(uint16_t*)&a, ub = *(uint16_t*)&b;
    return (uint32_t)ua | ((uint32_t)ub << 16);
}
__device__ __forceinline__ void split1(float v, __nv_bfloat16& h, __nv_bfloat16& l) {
    h = __float2bfloat16_rn(v);
    l = __float2bfloat16_rn(v - __bfloat162float(h));
}
__device__ __forceinline__ void mma16816(float* d, const uint32_t* a, const uint32_t* b) {
    asm volatile(
        "mma.sync.aligned.m16n8k16.row.col.f32.bf16.bf16.f32 "
        "{%0,%1,%2,%3}, {%4,%5,%6,%7}, {%8,%9}, {%0,%1,%2,%3};"
        : "+f"(d[0]), "+f"(d[1]), "+f"(d[2]), "+f"(d[3])
        : "r"(a[0]), "r"(a[1]), "r"(a[2]), "r"(a[3]), "r"(b[0]), "r"(b[1]));
}

// ---------------- CSR construction ----------------
__global__ void k_zero() {
    int i = blockIdx.x * blockDim.x + threadIdx.x;
    if (i < N_NODES) g_deg[i] = 0;
    if (i <= SCAN_NB) { g_ready[i] = 0; g_pref[i] = 0; }
}

// hist (blocks [0, EB)) + weight split (blocks [EB, EB+64))
#define EB ((N_EDGES + 255) / 256)
__global__ void k_hist_splitw(const int* __restrict__ ei,
                              const float* __restrict__ W0, const float* __restrict__ W1,
                              const float* __restrict__ W2, const float* __restrict__ W3) {
    int b = blockIdx.x;
    if (b < EB) {
        int e = b * 256 + threadIdx.x;
        if (e < N_EDGES) {
            int dst = ei[N_EDGES + e];
            if (dst >= 0 && dst < N_NODES) atomicAdd(&g_deg[dst], 1);
        }
    } else {
        int i = (b - EB) * 256 + threadIdx.x;    // 0..16383 float4 units
        int m = i >> 12, o = (i & 4095) * 4;
        const float* W = (m == 0) ? W0 : (m == 1) ? W1 : (m == 2) ? W2 : W3;
        float4 v = ((const float4*)(W + o))[0];
        __nv_bfloat16 h0, h1, h2, h3, l0, l1, l2, l3;
        split1(v.x, h0, l0); split1(v.y, h1, l1); split1(v.z, h2, l2); split1(v.w, h3, l3);
        *(uint2*)(g_whi + m * 16384 + o) = make_uint2(pack2(h0, h1), pack2(h2, h3));
        *(uint2*)(g_wlo + m * 16384 + o) = make_uint2(pack2(l0, l1), pack2(l2, l3));
    }
}

// single-pass exclusive scan with decoupled chain lookback (98 blocks, all resident)
__global__ void k_scan() {
    __shared__ int s[SCAN_BS];
    __shared__ int blk_prefix;
    int b = blockIdx.x;
    int i = b * SCAN_BS + threadIdx.x;
    int v = (i < N_NODES) ? g_deg[i] : 0;
    s[threadIdx.x] = v;
    __syncthreads();
    for (int off = 1; off < SCAN_BS; off <<= 1) {
        int t = 0;
        if ((int)threadIdx.x >= off) t = s[threadIdx.x - off];
        __syncthreads();
        s[threadIdx.x] += t;
        __syncthreads();
    }
    int incl = s[threadIdx.x];
    if (threadIdx.x == 0) {
        int total = s[SCAN_BS - 1];
        int pre;
        if (b == 0) {
            pre = 0;
        } else {
            while (atomicAdd(&g_ready[b], 0) == 0) { }   // spin on predecessor
            pre = g_pref[b];
        }
        g_pref[b + 1] = pre + total;
        __threadfence();
        atomicExch(&g_ready[b + 1], 1);
        blk_prefix = pre;
    }
    __syncthreads();
    int excl = blk_prefix + incl - v;
    if (i < N_NODES) {
        g_rowoff[i] = excl;
        g_cursor[i] = excl;
    }
    if (i == 0) g_rowoff[N_NODES] = N_EDGES;
}

__global__ void k_fill(const int* __restrict__ ei) {
    int e = blockIdx.x * blockDim.x + threadIdx.x;
    if (e < N_EDGES) {
        int src = ei[e];
        int dst = ei[N_EDGES + e];
        if (dst >= 0 && dst < N_NODES && src >= 0 && src < N_NODES) {
            int pos = atomicAdd(&g_cursor[dst], 1);
            g_csr[pos] = src;
        }
    }
}

// ---------------- mean aggregation (warp/node) + optional fused x split ----------------
__global__ void k_agg(const float* __restrict__ X,
                      __nv_bfloat16* __restrict__ ohi, __nv_bfloat16* __restrict__ olo,
                      __nv_bfloat16* __restrict__ xhi, __nv_bfloat16* __restrict__ xlo) {
    int node = (blockIdx.x * blockDim.x + threadIdx.x) >> 5;
    int lane = threadIdx.x & 31;
    if (node >= NP) return;
    float4 acc = make_float4(0.f, 0.f, 0.f, 0.f);
    float4 xv = make_float4(0.f, 0.f, 0.f, 0.f);
    if (node < N_NODES) {
        int s = g_rowoff[node];
        int e = g_rowoff[node + 1];
        for (int j = s; j < e; j++) {
            int src = g_csr[j];                               // warp-uniform broadcast
            float4 v = ((const float4*)(X + (size_t)src * 128))[lane];
            acc.x += v.x; acc.y += v.y; acc.z += v.z; acc.w += v.w;
        }
        float inv = 1.0f / (float)max(e - s, 1);
        acc.x *= inv; acc.y *= inv; acc.z *= inv; acc.w *= inv;
        if (xhi) xv = ((const float4*)(X + (size_t)node * 128))[lane];
    }
    size_t off = (size_t)node * 128 + lane * 4;
    {
        __nv_bfloat16 h0, h1, h2, h3, l0, l1, l2, l3;
        split1(acc.x, h0, l0); split1(acc.y, h1, l1); split1(acc.z, h2, l2); split1(acc.w, h3, l3);
        *(uint2*)(ohi + off) = make_uint2(pack2(h0, h1), pack2(h2, h3));
        *(uint2*)(olo + off) = make_uint2(pack2(l0, l1), pack2(l2, l3));
    }
    if (xhi) {
        __nv_bfloat16 h0, h1, h2, h3, l0, l1, l2, l3;
        split1(xv.x, h0, l0); split1(xv.y, h1, l1); split1(xv.z, h2, l2); split1(xv.w, h3, l3);
        *(uint2*)(xhi + off) = make_uint2(pack2(h0, h1), pack2(h2, h3));
        *(uint2*)(xlo + off) = make_uint2(pack2(l0, l1), pack2(l2, l3));
    }
}

// ---------------- HMMA GEMM: out = relu(A0 W0^T + A1 W1^T + bias) ----------------
// 128x128 CTA tile; smem: Ah/Al/Wh/Wl 32KB each, 16B-chunk XOR swizzle (c ^ (r&7)).
// Scalar LDS fragment loads (proven conflict-free); fp32 accum; 3 split terms.
#define SM_AH 0
#define SM_AL 32768
#define SM_WH 65536
#define SM_WL 98304
#define SMEM_GEMM 131072

__device__ __forceinline__ void load_mat(char* sm, const __nv_bfloat16* __restrict__ g, int row0) {
    int tid = threadIdx.x;
#pragma unroll
    for (int i = 0; i < 8; i++) {
        int idx = tid + i * 256;           // 0..2047 chunks
        int r = idx >> 4, c = idx & 15;
        uint4 v = *(const uint4*)((const char*)(g + (size_t)(row0 + r) * 128) + c * 16);
        *(uint4*)(sm + r * 256 + (((c ^ (r & 7)) << 4))) = v;
    }
}
__device__ __forceinline__ uint32_t ldsb(const char* m, int row, int k) {
    int addr = row * 256 + ((((k >> 3) ^ (row & 7)) << 4)) + ((k & 7) << 1);
    return *(const uint32_t*)(m + addr);
}

__global__ __launch_bounds__(256, 1) void k_tgemm(
    const __nv_bfloat16* __restrict__ A0h, const __nv_bfloat16* __restrict__ A0l,
    const __nv_bfloat16* __restrict__ A1h, const __nv_bfloat16* __restrict__ A1l,
    const __nv_bfloat16* __restrict__ W0h, const __nv_bfloat16* __restrict__ W0l,
    const __nv_bfloat16* __restrict__ W1h, const __nv_bfloat16* __restrict__ W1l,
    const float* __restrict__ bias, float* __restrict__ outf,
    __nv_bfloat16* __restrict__ ohi, __nv_bfloat16* __restrict__ olo, int write_split)
{
    extern __shared__ __align__(16) char sm[];
    int tid = threadIdx.x, wid = tid >> 5, lane = tid & 31;
    int n0 = blockIdx.x * 128;
    int mwarp = (wid & 3) * 32;        // M offset of warp tile
    int nwarp = (wid >> 2) * 64;       // N offset of warp tile
    int tr = lane >> 2, tc = lane & 3;

    float acc[2][8][4];
#pragma unroll
    for (int m = 0; m < 2; m++)
#pragma unroll
        for (int n = 0; n < 8; n++)
#pragma unroll
            for (int q = 0; q < 4; q++) acc[m][n][q] = 0.f;

    for (int phase = 0; phase < 2; phase++) {
        if (phase) __syncthreads();
        load_mat(sm + SM_AH, phase ? A1h : A0h, n0);
        load_mat(sm + SM_AL, phase ? A1l : A0l, n0);
        load_mat(sm + SM_WH, phase ? W1h : W0h, 0);
        load_mat(sm + SM_WL, phase ? W1l : W0l, 0);
        __syncthreads();

        const char* Ah = sm + SM_AH;
        const char* Al = sm + SM_AL;
        const char* Wh = sm + SM_WH;
        const char* Wl = sm + SM_WL;

#pragma unroll
        for (int k0 = 0; k0 < 128; k0 += 16) {
            uint32_t ah[2][4], al[2][4], bh[8][2], bl[8][2];
#pragma unroll
            for (int m = 0; m < 2; m++) {
                int row = mwarp + m * 16 + tr;
                ah[m][0] = ldsb(Ah, row,     k0 + tc * 2);
                ah[m][1] = ldsb(Ah, row + 8, k0 + tc * 2);
                ah[m][2] = ldsb(Ah, row,     k0 + tc * 2 + 8);
                ah[m][3] = ldsb(Ah, row + 8, k0 + tc * 2 + 8);
                al[m][0] = ldsb(Al, row,     k0 + tc * 2);
                al[m][1] = ldsb(Al, row + 8, k0 + tc * 2);
                al[m][2] = ldsb(Al, row,     k0 + tc * 2 + 8);
                al[m][3] = ldsb(Al, row + 8, k0 + tc * 2 + 8);
            }
#pragma unroll
            for (int n = 0; n < 8; n++) {
                int wr = nwarp + n * 8 + tr;
                bh[n][0] = ldsb(Wh, wr, k0 + tc * 2);
                bh[n][1] = ldsb(Wh, wr, k0 + tc * 2 + 8);
                bl[n][0] = ldsb(Wl, wr, k0 + tc * 2);
                bl[n][1] = ldsb(Wl, wr, k0 + tc * 2 + 8);
            }
#pragma unroll
            for (int m = 0; m < 2; m++)
#pragma unroll
                for (int n = 0; n < 8; n++) {
                    mma16816(acc[m][n], ah[m], bh[n]);   // hi*hi
                    mma16816(acc[m][n], ah[m], bl[n]);   // hi*lo
                    mma16816(acc[m][n], al[m], bh[n]);   // lo*hi
                }
        }
    }

    // epilogue: bias + relu (+ optional bf16 split write)
#pragma unroll
    for (int m = 0; m < 2; m++) {
#pragma unroll
        for (int half = 0; half < 2; half++) {
            int row = n0 + mwarp + m * 16 + half * 8 + tr;
            if (row < N_NODES) {
#pragma unroll
                for (int n = 0; n < 8; n++) {
                    int c = nwarp + n * 8 + tc * 2;
                    float v0 = fmaxf(acc[m][n][half * 2 + 0] + bias[c], 0.f);
                    float v1 = fmaxf(acc[m][n][half * 2 + 1] + bias[c + 1], 0.f);
                    *(float2*)(outf + (size_t)row * 128 + c) = make_float2(v0, v1);
                    if (write_split) {
                        __nv_bfloat16 h0, l0, h1b, l1b;
                        split1(v0, h0, l0);
                        split1(v1, h1b, l1b);
                        *(uint32_t*)(ohi + (size_t)row * 128 + c) = pack2(h0, h1b);
                        *(uint32_t*)(olo + (size_t)row * 128 + c) = pack2(l0, l1b);
                    }
                }
            }
        }
    }
}

// ---------------- fused pool + final linear (one block per graph) ----------------
__device__ __forceinline__ int lbound32(const int* __restrict__ a, int n, int v) {
    int lo = 0, hi = n;
    while (lo < hi) {
        int mid = (lo + hi) >> 1;
        if (a[mid] < v) lo = mid + 1; else hi = mid;
    }
    return lo;
}
__global__ void k_poolfinal(const int* __restrict__ batch,
                            const float* __restrict__ Wlin, const float* __restrict__ blin,
                            float* __restrict__ out) {
    __shared__ float pooled[128];
    int g = blockIdx.x, t = threadIdx.x;     // 64 blocks, 128 threads
    int s = lbound32(batch, N_NODES, g);
    int e = lbound32(batch, N_NODES, g + 1);
    float sum = 0.f;
    int n = s;
    for (; n + 3 < e; n += 4) {
        sum += g_h2[(size_t)n * 128 + t];
        sum += g_h2[(size_t)(n + 1) * 128 + t];
        sum += g_h2[(size_t)(n + 2) * 128 + t];
        sum += g_h2[(size_t)(n + 3) * 128 + t];
    }
    for (; n < e; n++) sum += g_h2[(size_t)n * 128 + t];
    pooled[t] = sum / (float)max(e - s, 1);
    __syncthreads();
    if (t < 32) {
        float v = 0.f;
#pragma unroll 8
        for (int k = 0; k < 128; k++)
            v += pooled[k] * Wlin[t * 128 + k];
        out[g * 32 + t] = v + blin[t];
    }
}

// ---------------- launch ----------------
extern "C" void kernel_launch(void* const* d_in, const int* in_sizes, int n_in,
                              void* d_out, int out_size) {
    const float* x     = (const float*)d_in[0];
    const int*   ei    = (const int*)d_in[1];
    const int*   batch = (const int*)d_in[2];
    const float* W1l  = (const float*)d_in[3];
    const float* b1   = (const float*)d_in[4];
    const float* W1r  = (const float*)d_in[5];
    const float* W2l  = (const float*)d_in[6];
    const float* b2   = (const float*)d_in[7];
    const float* W2r  = (const float*)d_in[8];
    const float* Wlin = (const float*)d_in[9];
    const float* blin = (const float*)d_in[10];
    float* out = (float*)d_out;

    void *p;
    cudaGetSymbolAddress(&p, g_xhi);  __nv_bfloat16* xhi = (__nv_bfloat16*)p;
    cudaGetSymbolAddress(&p, g_xlo);  __nv_bfloat16* xlo = (__nv_bfloat16*)p;
    cudaGetSymbolAddress(&p, g_mhi);  __nv_bfloat16* mhi = (__nv_bfloat16*)p;
    cudaGetSymbolAddress(&p, g_mlo);  __nv_bfloat16* mlo = (__nv_bfloat16*)p;
    cudaGetSymbolAddress(&p, g_h1hi); __nv_bfloat16* h1hi = (__nv_bfloat16*)p;
    cudaGetSymbolAddress(&p, g_h1lo); __nv_bfloat16* h1lo = (__nv_bfloat16*)p;
    cudaGetSymbolAddress(&p, g_whi);  __nv_bfloat16* whi = (__nv_bfloat16*)p;
    cudaGetSymbolAddress(&p, g_wlo);  __nv_bfloat16* wlo = (__nv_bfloat16*)p;
    cudaGetSymbolAddress(&p, g_h1);   float* h1 = (float*)p;
    cudaGetSymbolAddress(&p, g_h2);   float* h2 = (float*)p;

    cudaFuncSetAttribute(k_tgemm, cudaFuncAttributeMaxDynamicSharedMemorySize, SMEM_GEMM);

    const int GEMM_GRID = NP / 128;       // 391
    const int AGG_GRID = NP / 8;          // warp per node, 256 thr/block

    // CSR build (4 launches)
    k_zero<<<(N_NODES + 255) / 256, 256>>>();
    k_hist_splitw<<<EB + 64, 256>>>(ei, W1l, W1r, W2l, W2r);
    k_scan<<<SCAN_NB, SCAN_BS>>>();
    k_fill<<<EB, 256>>>(ei);

    // layer 1 (agg fused with x split)
    k_agg<<<AGG_GRID, 256>>>(x, mhi, mlo, xhi, xlo);
    k_tgemm<<<GEMM_GRID, 256, SMEM_GEMM>>>(mhi, mlo, xhi, xlo,
                                           whi + 0, wlo + 0, whi + 16384, wlo + 16384,
                                           b1, h1, h1hi, h1lo, 1);
    // layer 2
    k_agg<<<AGG_GRID, 256>>>(h1, mhi, mlo, (__nv_bfloat16*)0, (__nv_bfloat16*)0);
    k_tgemm<<<GEMM_GRID, 256, SMEM_GEMM>>>(mhi, mlo, h1hi, h1lo,
                                           whi + 32768, wlo + 32768, whi + 49152, wlo + 49152,
                                           b2, h2, h1hi, h1lo, 0);

    // fused pool + final linear
    k_poolfinal<<<N_GRAPHS, 128>>>(batch, Wlin, blin, out);
}

// round 14
// speedup vs baseline: 1.4422x; 1.4422x over previous
#include <cuda_runtime.h>
#include <cuda_bf16.h>
#include <cstdint>

#define N_NODES 50000
#define NP      50048          /* padded to 391*128 */
#define N_EDGES 600000
#define IN_C 128
#define HID 128
#define OUT_C 32
#define N_GRAPHS 64

#define SCAN_BS 512
#define SCAN_NB ((N_NODES + SCAN_BS - 1) / SCAN_BS)   // 98

// ---------------- scratch (static device globals) ----------------
__device__ int   g_deg[N_NODES];
__device__ int   g_rowoff[N_NODES + 1];
__device__ int   g_cursor[N_NODES];
__device__ int   g_csr[N_EDGES];
__device__ int   g_bsum[SCAN_NB + 8];
__device__ __align__(16) __nv_bfloat16 g_xhi[(size_t)NP * 128], g_xlo[(size_t)NP * 128];
__device__ __align__(16) __nv_bfloat16 g_mhi[(size_t)NP * 128], g_mlo[(size_t)NP * 128];
__device__ __align__(16) __nv_bfloat16 g_h1hi[(size_t)NP * 128], g_h1lo[(size_t)NP * 128];
__device__ __align__(16) __nv_bfloat16 g_whi[4 * 128 * 128], g_wlo[4 * 128 * 128];
__device__ __align__(16) float g_h1[(size_t)NP * 128];
__device__ __align__(16) float g_h2[(size_t)N_NODES * 128];

// ---------------- helpers ----------------
__device__ __forceinline__ uint32_t pack2(__nv_bfloat16 a, __nv_bfloat16 b) {
    uint16_t ua = *(uint16_t*)&a, ub = *(uint16_t*)&b;
    return (uint32_t)ua | ((uint32_t)ub << 16);
}
__device__ __forceinline__ void split1(float v, __nv_bfloat16& h, __nv_bfloat16& l) {
    h = __float2bfloat16_rn(v);
    l = __float2bfloat16_rn(v - __bfloat162float(h));
}
__device__ __forceinline__ void mma16816(float* d, const uint32_t* a, const uint32_t* b) {
    asm volatile(
        "mma.sync.aligned.m16n8k16.row.col.f32.bf16.bf16.f32 "
        "{%0,%1,%2,%3}, {%4,%5,%6,%7}, {%8,%9}, {%0,%1,%2,%3};"
        : "+f"(d[0]), "+f"(d[1]), "+f"(d[2]), "+f"(d[3])
        : "r"(a[0]), "r"(a[1]), "r"(a[2]), "r"(a[3]), "r"(b[0]), "r"(b[1]));
}

// ---------------- CSR construction ----------------
__global__ void k_zero() {
    int i = blockIdx.x * blockDim.x + threadIdx.x;
    if (i < N_NODES) g_deg[i] = 0;
}

// hist (blocks [0, EB)) + weight split (blocks [EB, EB+64))
#define EB ((N_EDGES + 255) / 256)
__global__ void k_hist_splitw(const int* __restrict__ ei,
                              const float* __restrict__ W0, const float* __restrict__ W1,
                              const float* __restrict__ W2, const float* __restrict__ W3) {
    int b = blockIdx.x;
    if (b < EB) {
        int e = b * 256 + threadIdx.x;
        if (e < N_EDGES) {
            int dst = ei[N_EDGES + e];
            if (dst >= 0 && dst < N_NODES) atomicAdd(&g_deg[dst], 1);
        }
    } else {
        int i = (b - EB) * 256 + threadIdx.x;    // 0..16383 float4 units
        int m = i >> 12, o = (i & 4095) * 4;
        const float* W = (m == 0) ? W0 : (m == 1) ? W1 : (m == 2) ? W2 : W3;
        float4 v = ((const float4*)(W + o))[0];
        __nv_bfloat16 h0, h1, h2, h3, l0, l1, l2, l3;
        split1(v.x, h0, l0); split1(v.y, h1, l1); split1(v.z, h2, l2); split1(v.w, h3, l3);
        *(uint2*)(g_whi + m * 16384 + o) = make_uint2(pack2(h0, h1), pack2(h2, h3));
        *(uint2*)(g_wlo + m * 16384 + o) = make_uint2(pack2(l0, l1), pack2(l2, l3));
    }
}

__global__ void k_scan1() {
    __shared__ int s[SCAN_BS];
    int i = blockIdx.x * SCAN_BS + threadIdx.x;
    int v = (i < N_NODES) ? g_deg[i] : 0;
    s[threadIdx.x] = v;
    __syncthreads();
    for (int off = 1; off < SCAN_BS; off <<= 1) {
        int t = 0;
        if ((int)threadIdx.x >= off) t = s[threadIdx.x - off];
        __syncthreads();
        s[threadIdx.x] += t;
        __syncthreads();
    }
    int incl = s[threadIdx.x];
    if (i < N_NODES) g_rowoff[i] = incl - v;
    if (threadIdx.x == SCAN_BS - 1) g_bsum[blockIdx.x] = incl;
}
__global__ void k_scan2() {
    __shared__ int ws[4];
    int t = threadIdx.x;
    int v = (t < SCAN_NB) ? g_bsum[t] : 0;
    int x = v;
    for (int o = 1; o < 32; o <<= 1) {
        int y = __shfl_up_sync(0xFFFFFFFFu, x, o);
        if ((t & 31) >= o) x += y;
    }
    if ((t & 31) == 31) ws[t >> 5] = x;
    __syncthreads();
    if (t == 0) {
        int run = 0;
        for (int w = 0; w < 4; w++) { int tmp = ws[w]; ws[w] = run; run += tmp; }
    }
    __syncthreads();
    int excl = x - v + ws[t >> 5];
    if (t < SCAN_NB) g_bsum[t] = excl;
}
__global__ void k_scan3() {
    int i = blockIdx.x * SCAN_BS + threadIdx.x;
    if (i < N_NODES) {
        int v = g_rowoff[i] + g_bsum[blockIdx.x];
        g_rowoff[i] = v;
        g_cursor[i] = v;
    }
    if (i == 0) g_rowoff[N_NODES] = N_EDGES;
}

__global__ void k_fill(const int* __restrict__ ei) {
    int e = blockIdx.x * blockDim.x + threadIdx.x;
    if (e < N_EDGES) {
        int src = ei[e];
        int dst = ei[N_EDGES + e];
        if (dst >= 0 && dst < N_NODES && src >= 0 && src < N_NODES) {
            int pos = atomicAdd(&g_cursor[dst], 1);
            g_csr[pos] = src;
        }
    }
}

// ---------------- mean aggregation (warp/node) + optional fused x split ----------------
__global__ void k_agg(const float* __restrict__ X,
                      __nv_bfloat16* __restrict__ ohi, __nv_bfloat16* __restrict__ olo,
                      __nv_bfloat16* __restrict__ xhi, __nv_bfloat16* __restrict__ xlo) {
    int node = (blockIdx.x * blockDim.x + threadIdx.x) >> 5;
    int lane = threadIdx.x & 31;
    if (node >= NP) return;
    float4 acc = make_float4(0.f, 0.f, 0.f, 0.f);
    float4 xv = make_float4(0.f, 0.f, 0.f, 0.f);
    if (node < N_NODES) {
        int s = g_rowoff[node];
        int e = g_rowoff[node + 1];
        for (int j = s; j < e; j++) {
            int src = g_csr[j];                               // warp-uniform broadcast
            float4 v = ((const float4*)(X + (size_t)src * 128))[lane];
            acc.x += v.x; acc.y += v.y; acc.z += v.z; acc.w += v.w;
        }
        float inv = 1.0f / (float)max(e - s, 1);
        acc.x *= inv; acc.y *= inv; acc.z *= inv; acc.w *= inv;
        if (xhi) xv = ((const float4*)(X + (size_t)node * 128))[lane];
    }
    size_t off = (size_t)node * 128 + lane * 4;
    {
        __nv_bfloat16 h0, h1, h2, h3, l0, l1, l2, l3;
        split1(acc.x, h0, l0); split1(acc.y, h1, l1); split1(acc.z, h2, l2); split1(acc.w, h3, l3);
        *(uint2*)(ohi + off) = make_uint2(pack2(h0, h1), pack2(h2, h3));
        *(uint2*)(olo + off) = make_uint2(pack2(l0, l1), pack2(l2, l3));
    }
    if (xhi) {
        __nv_bfloat16 h0, h1, h2, h3, l0, l1, l2, l3;
        split1(xv.x, h0, l0); split1(xv.y, h1, l1); split1(xv.z, h2, l2); split1(xv.w, h3, l3);
        *(uint2*)(xhi + off) = make_uint2(pack2(h0, h1), pack2(h2, h3));
        *(uint2*)(xlo + off) = make_uint2(pack2(l0, l1), pack2(l2, l3));
    }
}

// ---------------- HMMA GEMM: out = relu(A0 W0^T + A1 W1^T + bias) ----------------
// 128x128 CTA tile; smem: Ah/Al/Wh/Wl 32KB each, 16B-chunk XOR swizzle (c ^ (r&7)).
// Scalar LDS fragment loads (proven conflict-free); fp32 accum; 3 split terms.
#define SM_AH 0
#define SM_AL 32768
#define SM_WH 65536
#define SM_WL 98304
#define SMEM_GEMM 131072

__device__ __forceinline__ void load_mat(char* sm, const __nv_bfloat16* __restrict__ g, int row0) {
    int tid = threadIdx.x;
#pragma unroll
    for (int i = 0; i < 8; i++) {
        int idx = tid + i * 256;           // 0..2047 chunks
        int r = idx >> 4, c = idx & 15;
        uint4 v = *(const uint4*)((const char*)(g + (size_t)(row0 + r) * 128) + c * 16);
        *(uint4*)(sm + r * 256 + (((c ^ (r & 7)) << 4))) = v;
    }
}
__device__ __forceinline__ uint32_t ldsb(const char* m, int row, int k) {
    int addr = row * 256 + ((((k >> 3) ^ (row & 7)) << 4)) + ((k & 7) << 1);
    return *(const uint32_t*)(m + addr);
}

__global__ __launch_bounds__(256, 1) void k_tgemm(
    const __nv_bfloat16* __restrict__ A0h, const __nv_bfloat16* __restrict__ A0l,
    const __nv_bfloat16* __restrict__ A1h, const __nv_bfloat16* __restrict__ A1l,
    const __nv_bfloat16* __restrict__ W0h, const __nv_bfloat16* __restrict__ W0l,
    const __nv_bfloat16* __restrict__ W1h, const __nv_bfloat16* __restrict__ W1l,
    const float* __restrict__ bias, float* __restrict__ outf,
    __nv_bfloat16* __restrict__ ohi, __nv_bfloat16* __restrict__ olo, int write_split)
{
    extern __shared__ __align__(16) char sm[];
    int tid = threadIdx.x, wid = tid >> 5, lane = tid & 31;
    int n0 = blockIdx.x * 128;
    int mwarp = (wid & 3) * 32;        // M offset of warp tile
    int nwarp = (wid >> 2) * 64;       // N offset of warp tile
    int tr = lane >> 2, tc = lane & 3;

    float acc[2][8][4];
#pragma unroll
    for (int m = 0; m < 2; m++)
#pragma unroll
        for (int n = 0; n < 8; n++)
#pragma unroll
            for (int q = 0; q < 4; q++) acc[m][n][q] = 0.f;

    for (int phase = 0; phase < 2; phase++) {
        if (phase) __syncthreads();
        load_mat(sm + SM_AH, phase ? A1h : A0h, n0);
        load_mat(sm + SM_AL, phase ? A1l : A0l, n0);
        load_mat(sm + SM_WH, phase ? W1h : W0h, 0);
        load_mat(sm + SM_WL, phase ? W1l : W0l, 0);
        __syncthreads();

        const char* Ah = sm + SM_AH;
        const char* Al = sm + SM_AL;
        const char* Wh = sm + SM_WH;
        const char* Wl = sm + SM_WL;

#pragma unroll
        for (int k0 = 0; k0 < 128; k0 += 16) {
            uint32_t ah[2][4], al[2][4], bh[8][2], bl[8][2];
#pragma unroll
            for (int m = 0; m < 2; m++) {
                int row = mwarp + m * 16 + tr;
                ah[m][0] = ldsb(Ah, row,     k0 + tc * 2);
                ah[m][1] = ldsb(Ah, row + 8, k0 + tc * 2);
                ah[m][2] = ldsb(Ah, row,     k0 + tc * 2 + 8);
                ah[m][3] = ldsb(Ah, row + 8, k0 + tc * 2 + 8);
                al[m][0] = ldsb(Al, row,     k0 + tc * 2);
                al[m][1] = ldsb(Al, row + 8, k0 + tc * 2);
                al[m][2] = ldsb(Al, row,     k0 + tc * 2 + 8);
                al[m][3] = ldsb(Al, row + 8, k0 + tc * 2 + 8);
            }
#pragma unroll
            for (int n = 0; n < 8; n++) {
                int wr = nwarp + n * 8 + tr;
                bh[n][0] = ldsb(Wh, wr, k0 + tc * 2);
                bh[n][1] = ldsb(Wh, wr, k0 + tc * 2 + 8);
                bl[n][0] = ldsb(Wl, wr, k0 + tc * 2);
                bl[n][1] = ldsb(Wl, wr, k0 + tc * 2 + 8);
            }
#pragma unroll
            for (int m = 0; m < 2; m++)
#pragma unroll
                for (int n = 0; n < 8; n++) {
                    mma16816(acc[m][n], ah[m], bh[n]);   // hi*hi
                    mma16816(acc[m][n], ah[m], bl[n]);   // hi*lo
                    mma16816(acc[m][n], al[m], bh[n]);   // lo*hi
                }
        }
    }

    // epilogue: bias + relu (+ optional bf16 split write)
#pragma unroll
    for (int m = 0; m < 2; m++) {
#pragma unroll
        for (int half = 0; half < 2; half++) {
            int row = n0 + mwarp + m * 16 + half * 8 + tr;
            if (row < N_NODES) {
#pragma unroll
                for (int n = 0; n < 8; n++) {
                    int c = nwarp + n * 8 + tc * 2;
                    float v0 = fmaxf(acc[m][n][half * 2 + 0] + bias[c], 0.f);
                    float v1 = fmaxf(acc[m][n][half * 2 + 1] + bias[c + 1], 0.f);
                    *(float2*)(outf + (size_t)row * 128 + c) = make_float2(v0, v1);
                    if (write_split) {
                        __nv_bfloat16 h0, l0, h1b, l1b;
                        split1(v0, h0, l0);
                        split1(v1, h1b, l1b);
                        *(uint32_t*)(ohi + (size_t)row * 128 + c) = pack2(h0, h1b);
                        *(uint32_t*)(olo + (size_t)row * 128 + c) = pack2(l0, l1b);
                    }
                }
            }
        }
    }
}

// ---------------- fused pool + final linear (one block per graph) ----------------
__device__ __forceinline__ int lbound32(const int* __restrict__ a, int n, int v) {
    int lo = 0, hi = n;
    while (lo < hi) {
        int mid = (lo + hi) >> 1;
        if (a[mid] < v) lo = mid + 1; else hi = mid;
    }
    return lo;
}
__global__ void k_poolfinal(const int* __restrict__ batch,
                            const float* __restrict__ Wlin, const float* __restrict__ blin,
                            float* __restrict__ out) {
    __shared__ float pooled[128];
    int g = blockIdx.x, t = threadIdx.x;     // 64 blocks, 128 threads
    int s = lbound32(batch, N_NODES, g);
    int e = lbound32(batch, N_NODES, g + 1);
    float sum = 0.f;
    int n = s;
    for (; n + 3 < e; n += 4) {
        sum += g_h2[(size_t)n * 128 + t];
        sum += g_h2[(size_t)(n + 1) * 128 + t];
        sum += g_h2[(size_t)(n + 2) * 128 + t];
        sum += g_h2[(size_t)(n + 3) * 128 + t];
    }
    for (; n < e; n++) sum += g_h2[(size_t)n * 128 + t];
    pooled[t] = sum / (float)max(e - s, 1);
    __syncthreads();
    if (t < 32) {
        float v = 0.f;
#pragma unroll 8
        for (int k = 0; k < 128; k++)
            v += pooled[k] * Wlin[t * 128 + k];
        out[g * 32 + t] = v + blin[t];
    }
}

// ---------------- launch ----------------
extern "C" void kernel_launch(void* const* d_in, const int* in_sizes, int n_in,
                              void* d_out, int out_size) {
    const float* x     = (const float*)d_in[0];
    const int*   ei    = (const int*)d_in[1];
    const int*   batch = (const int*)d_in[2];
    const float* W1l  = (const float*)d_in[3];
    const float* b1   = (const float*)d_in[4];
    const float* W1r  = (const float*)d_in[5];
    const float* W2l  = (const float*)d_in[6];
    const float* b2   = (const float*)d_in[7];
    const float* W2r  = (const float*)d_in[8];
    const float* Wlin = (const float*)d_in[9];
    const float* blin = (const float*)d_in[10];
    float* out = (float*)d_out;

    void *p;
    cudaGetSymbolAddress(&p, g_xhi);  __nv_bfloat16* xhi = (__nv_bfloat16*)p;
    cudaGetSymbolAddress(&p, g_xlo);  __nv_bfloat16* xlo = (__nv_bfloat16*)p;
    cudaGetSymbolAddress(&p, g_mhi);  __nv_bfloat16* mhi = (__nv_bfloat16*)p;
    cudaGetSymbolAddress(&p, g_mlo);  __nv_bfloat16* mlo = (__nv_bfloat16*)p;
    cudaGetSymbolAddress(&p, g_h1hi); __nv_bfloat16* h1hi = (__nv_bfloat16*)p;
    cudaGetSymbolAddress(&p, g_h1lo); __nv_bfloat16* h1lo = (__nv_bfloat16*)p;
    cudaGetSymbolAddress(&p, g_whi);  __nv_bfloat16* whi = (__nv_bfloat16*)p;
    cudaGetSymbolAddress(&p, g_wlo);  __nv_bfloat16* wlo = (__nv_bfloat16*)p;
    cudaGetSymbolAddress(&p, g_h1);   float* h1 = (float*)p;
    cudaGetSymbolAddress(&p, g_h2);   float* h2 = (float*)p;

    cudaFuncSetAttribute(k_tgemm, cudaFuncAttributeMaxDynamicSharedMemorySize, SMEM_GEMM);

    const int GEMM_GRID = NP / 128;       // 391
    const int AGG_GRID = NP / 8;          // warp per node, 256 thr/block

    // CSR build
    k_zero<<<(N_NODES + 255) / 256, 256>>>();
    k_hist_splitw<<<EB + 64, 256>>>(ei, W1l, W1r, W2l, W2r);
    k_scan1<<<SCAN_NB, SCAN_BS>>>();
    k_scan2<<<1, 128>>>();
    k_scan3<<<SCAN_NB, SCAN_BS>>>();
    k_fill<<<EB, 256>>>(ei);

    // layer 1 (agg fused with x split)
    k_agg<<<AGG_GRID, 256>>>(x, mhi, mlo, xhi, xlo);
    k_tgemm<<<GEMM_GRID, 256, SMEM_GEMM>>>(mhi, mlo, xhi, xlo,
                                           whi + 0, wlo + 0, whi + 16384, wlo + 16384,
                                           b1, h1, h1hi, h1lo, 1);
    // layer 2
    k_agg<<<AGG_GRID, 256>>>(h1, mhi, mlo, (__nv_bfloat16*)0, (__nv_bfloat16*)0);
    k_tgemm<<<GEMM_GRID, 256, SMEM_GEMM>>>(mhi, mlo, h1hi, h1lo,
                                           whi + 32768, wlo + 32768, whi + 49152, wlo + 49152,
                                           b2, h2, h1hi, h1lo, 0);

    // fused pool + final linear
    k_poolfinal<<<N_GRAPHS, 128>>>(batch, Wlin, blin, out);
}

// round 15
// speedup vs baseline: 1.7437x; 1.2090x over previous
#include <cuda_runtime.h>
#include <cuda_bf16.h>
#include <cstdint>

#define N_NODES 50000
#define NP      50048          /* padded to 391*128 */
#define N_EDGES 600000
#define IN_C 128
#define HID 128
#define OUT_C 32
#define N_GRAPHS 64

#define SCAN_BS 512
#define SCAN_NB ((N_NODES + SCAN_BS - 1) / SCAN_BS)   // 98

// ---------------- scratch (static device globals) ----------------
__device__ int   g_deg[N_NODES];
__device__ int   g_rowoff[N_NODES + 1];
__device__ int   g_cursor[N_NODES];
__device__ int   g_csr[N_EDGES];
__device__ int   g_bsum[SCAN_NB + 8];
__device__ __align__(16) __nv_bfloat16 g_xhi[(size_t)NP * 128], g_xlo[(size_t)NP * 128];
__device__ __align__(16) __nv_bfloat16 g_mhi[(size_t)NP * 128], g_mlo[(size_t)NP * 128];
__device__ __align__(16) __nv_bfloat16 g_h1hi[(size_t)NP * 128], g_h1lo[(size_t)NP * 128];
__device__ __align__(16) __nv_bfloat16 g_whi[4 * 128 * 128], g_wlo[4 * 128 * 128];
__device__ __align__(16) float g_h1[(size_t)NP * 128];
__device__ __align__(16) float g_h2[(size_t)N_NODES * 128];
__device__ float g_psum[4][N_GRAPHS][128];
__device__ int   g_cnt[N_GRAPHS];

// ---------------- helpers ----------------
__device__ __forceinline__ uint32_t smem_u32(const void* p) {
    uint32_t a;
    asm("{ .reg .u64 t; cvta.to.shared.u64 t, %1; cvt.u32.u64 %0, t; }" : "=r"(a) : "l"(p));
    return a;
}
__device__ __forceinline__ uint32_t pack2(__nv_bfloat16 a, __nv_bfloat16 b) {
    uint16_t ua = *(uint16_t*)&a, ub = *(uint16_t*)&b;
    return (uint32_t)ua | ((uint32_t)ub << 16);
}
__device__ __forceinline__ void split1(float v, __nv_bfloat16& h, __nv_bfloat16& l) {
    h = __float2bfloat16_rn(v);
    l = __float2bfloat16_rn(v - __bfloat162float(h));
}
__device__ __forceinline__ void mma16816(float* d, const uint32_t* a, const uint32_t* b) {
    asm volatile(
        "mma.sync.aligned.m16n8k16.row.col.f32.bf16.bf16.f32 "
        "{%0,%1,%2,%3}, {%4,%5,%6,%7}, {%8,%9}, {%0,%1,%2,%3};"
        : "+f"(d[0]), "+f"(d[1]), "+f"(d[2]), "+f"(d[3])
        : "r"(a[0]), "r"(a[1]), "r"(a[2]), "r"(a[3]), "r"(b[0]), "r"(b[1]));
}
__device__ __forceinline__ void cp16(uint32_t d, const void* s) {
    asm volatile("cp.async.cg.shared.global [%0], [%1], 16;" :: "r"(d), "l"(s));
}

// ---------------- CSR construction ----------------
__global__ void k_zero() {
    int i = blockIdx.x * blockDim.x + threadIdx.x;
    if (i < N_NODES) g_deg[i] = 0;
}

// hist (blocks [0, EB)) + weight split (blocks [EB, EB+64))
#define EB ((N_EDGES + 255) / 256)
__global__ void k_hist_splitw(const int* __restrict__ ei,
                              const float* __restrict__ W0, const float* __restrict__ W1,
                              const float* __restrict__ W2, const float* __restrict__ W3) {
    int b = blockIdx.x;
    if (b < EB) {
        int e = b * 256 + threadIdx.x;
        if (e < N_EDGES) {
            int dst = ei[N_EDGES + e];
            if (dst >= 0 && dst < N_NODES) atomicAdd(&g_deg[dst], 1);
        }
    } else {
        int i = (b - EB) * 256 + threadIdx.x;    // 0..16383 float4 units
        int m = i >> 12, o = (i & 4095) * 4;
        const float* W = (m == 0) ? W0 : (m == 1) ? W1 : (m == 2) ? W2 : W3;
        float4 v = ((const float4*)(W + o))[0];
        __nv_bfloat16 h0, h1, h2, h3, l0, l1, l2, l3;
        split1(v.x, h0, l0); split1(v.y, h1, l1); split1(v.z, h2, l2); split1(v.w, h3, l3);
        *(uint2*)(g_whi + m * 16384 + o) = make_uint2(pack2(h0, h1), pack2(h2, h3));
        *(uint2*)(g_wlo + m * 16384 + o) = make_uint2(pack2(l0, l1), pack2(l2, l3));
    }
}

__global__ void k_scan1() {
    __shared__ int s[SCAN_BS];
    int i = blockIdx.x * SCAN_BS + threadIdx.x;
    int v = (i < N_NODES) ? g_deg[i] : 0;
    s[threadIdx.x] = v;
    __syncthreads();
    for (int off = 1; off < SCAN_BS; off <<= 1) {
        int t = 0;
        if ((int)threadIdx.x >= off) t = s[threadIdx.x - off];
        __syncthreads();
        s[threadIdx.x] += t;
        __syncthreads();
    }
    int incl = s[threadIdx.x];
    if (i < N_NODES) g_rowoff[i] = incl - v;
    if (threadIdx.x == SCAN_BS - 1) g_bsum[blockIdx.x] = incl;
}
__global__ void k_scan2() {
    __shared__ int ws[4];
    int t = threadIdx.x;
    int v = (t < SCAN_NB) ? g_bsum[t] : 0;
    int x = v;
    for (int o = 1; o < 32; o <<= 1) {
        int y = __shfl_up_sync(0xFFFFFFFFu, x, o);
        if ((t & 31) >= o) x += y;
    }
    if ((t & 31) == 31) ws[t >> 5] = x;
    __syncthreads();
    if (t == 0) {
        int run = 0;
        for (int w = 0; w < 4; w++) { int tmp = ws[w]; ws[w] = run; run += tmp; }
    }
    __syncthreads();
    int excl = x - v + ws[t >> 5];
    if (t < SCAN_NB) g_bsum[t] = excl;
}
__global__ void k_scan3() {
    int i = blockIdx.x * SCAN_BS + threadIdx.x;
    if (i < N_NODES) {
        int v = g_rowoff[i] + g_bsum[blockIdx.x];
        g_rowoff[i] = v;
        g_cursor[i] = v;
    }
    if (i == 0) g_rowoff[N_NODES] = N_EDGES;
}

__global__ void k_fill(const int* __restrict__ ei) {
    int e = blockIdx.x * blockDim.x + threadIdx.x;
    if (e < N_EDGES) {
        int src = ei[e];
        int dst = ei[N_EDGES + e];
        if (dst >= 0 && dst < N_NODES && src >= 0 && src < N_NODES) {
            int pos = atomicAdd(&g_cursor[dst], 1);
            g_csr[pos] = src;
        }
    }
}

// ---------------- mean aggregation (warp/node) + optional fused x split ----------------
__global__ void k_agg(const float* __restrict__ X,
                      __nv_bfloat16* __restrict__ ohi, __nv_bfloat16* __restrict__ olo,
                      __nv_bfloat16* __restrict__ xhi, __nv_bfloat16* __restrict__ xlo) {
    int node = (blockIdx.x * blockDim.x + threadIdx.x) >> 5;
    int lane = threadIdx.x & 31;
    if (node >= NP) return;
    float4 acc = make_float4(0.f, 0.f, 0.f, 0.f);
    float4 xv = make_float4(0.f, 0.f, 0.f, 0.f);
    if (node < N_NODES) {
        int s = g_rowoff[node];
        int e = g_rowoff[node + 1];
        for (int j = s; j < e; j++) {
            int src = g_csr[j];                               // warp-uniform broadcast
            float4 v = ((const float4*)(X + (size_t)src * 128))[lane];
            acc.x += v.x; acc.y += v.y; acc.z += v.z; acc.w += v.w;
        }
        float inv = 1.0f / (float)max(e - s, 1);
        acc.x *= inv; acc.y *= inv; acc.z *= inv; acc.w *= inv;
        if (xhi) xv = ((const float4*)(X + (size_t)node * 128))[lane];
    }
    size_t off = (size_t)node * 128 + lane * 4;
    {
        __nv_bfloat16 h0, h1, h2, h3, l0, l1, l2, l3;
        split1(acc.x, h0, l0); split1(acc.y, h1, l1); split1(acc.z, h2, l2); split1(acc.w, h3, l3);
        *(uint2*)(ohi + off) = make_uint2(pack2(h0, h1), pack2(h2, h3));
        *(uint2*)(olo + off) = make_uint2(pack2(l0, l1), pack2(l2, l3));
    }
    if (xhi) {
        __nv_bfloat16 h0, h1, h2, h3, l0, l1, l2, l3;
        split1(xv.x, h0, l0); split1(xv.y, h1, l1); split1(xv.z, h2, l2); split1(xv.w, h3, l3);
        *(uint2*)(xhi + off) = make_uint2(pack2(h0, h1), pack2(h2, h3));
        *(uint2*)(xlo + off) = make_uint2(pack2(l0, l1), pack2(l2, l3));
    }
}

// ---------------- HMMA GEMM: out = relu(A0 W0^T + A1 W1^T + bias) ----------------
// 4 pipelined stages (phase x K-half), double-buffered cp.async fills.
// Per stage: Ah/Al/Wh/Wl 128x64 bf16 tiles (16KB each, row=128B, XOR swizzle c^(r&7)).
// Scalar LDS fragment loads (proven pattern); fp32 accum; 3 split terms (hh, hl, lh).
#define MATB 16384                 // one matrix stage tile
#define BUFB (4 * MATB)            // 64KB stage buffer
#define SMEM_GEMM (2 * BUFB)       // 128KB double-buffered

__device__ __forceinline__ void load_stage(uint32_t smb, int buf,
                                           const __nv_bfloat16* __restrict__ a_h,
                                           const __nv_bfloat16* __restrict__ a_l,
                                           const __nv_bfloat16* __restrict__ w_h,
                                           const __nv_bfloat16* __restrict__ w_l,
                                           int n0, int kh) {
    int tid = threadIdx.x;
    uint32_t base = smb + buf * BUFB;
    const char* srcs[4] = {(const char*)a_h, (const char*)a_l,
                           (const char*)w_h, (const char*)w_l};
    int row0s[4] = {n0, n0, 0, 0};
#pragma unroll
    for (int m = 0; m < 4; m++) {
#pragma unroll
        for (int i = 0; i < 4; i++) {
            int idx = tid + i * 256;            // 0..1023 chunks (128 rows x 8)
            int r = idx >> 3, c = idx & 7;
            uint32_t dst = base + m * MATB + r * 128 + ((c ^ (r & 7)) << 4);
            cp16(dst, srcs[m] + (size_t)(row0s[m] + r) * 256 + kh * 128 + c * 16);
        }
    }
}
__device__ __forceinline__ uint32_t ldsb64(const char* mat, int row, int k) {
    int addr = row * 128 + ((((k >> 3) ^ (row & 7)) << 4)) + ((k & 7) << 1);
    return *(const uint32_t*)(mat + addr);
}

__global__ __launch_bounds__(256, 1) void k_tgemm(
    const __nv_bfloat16* __restrict__ A0h, const __nv_bfloat16* __restrict__ A0l,
    const __nv_bfloat16* __restrict__ A1h, const __nv_bfloat16* __restrict__ A1l,
    const __nv_bfloat16* __restrict__ W0h, const __nv_bfloat16* __restrict__ W0l,
    const __nv_bfloat16* __restrict__ W1h, const __nv_bfloat16* __restrict__ W1l,
    const float* __restrict__ bias, float* __restrict__ outf,
    __nv_bfloat16* __restrict__ ohi, __nv_bfloat16* __restrict__ olo, int write_split)
{
    extern __shared__ __align__(16) char sm[];
    const uint32_t smb = smem_u32(sm);
    int tid = threadIdx.x, wid = tid >> 5, lane = tid & 31;
    int n0 = blockIdx.x * 128;
    int mwarp = (wid & 3) * 32;        // M offset of warp tile
    int nwarp = (wid >> 2) * 64;       // N offset of warp tile
    int tr = lane >> 2, tc = lane & 3;

    float acc[2][8][4];
#pragma unroll
    for (int m = 0; m < 2; m++)
#pragma unroll
        for (int n = 0; n < 8; n++)
#pragma unroll
            for (int q = 0; q < 4; q++) acc[m][n][q] = 0.f;

    const __nv_bfloat16* Ah_s[2] = {A0h, A1h};
    const __nv_bfloat16* Al_s[2] = {A0l, A1l};
    const __nv_bfloat16* Wh_s[2] = {W0h, W1h};
    const __nv_bfloat16* Wl_s[2] = {W0l, W1l};

    // prologue: stage 0
    load_stage(smb, 0, Ah_s[0], Al_s[0], Wh_s[0], Wl_s[0], n0, 0);
    asm volatile("cp.async.commit_group;");

#pragma unroll
    for (int s = 0; s < 4; s++) {
        int buf = s & 1;
        if (s < 3) {
            int ph = (s + 1) >> 1, kh = (s + 1) & 1;
            load_stage(smb, (s + 1) & 1, Ah_s[ph], Al_s[ph], Wh_s[ph], Wl_s[ph], n0, kh);
            asm volatile("cp.async.commit_group;");
            asm volatile("cp.async.wait_group 1;" ::: "memory");
        } else {
            asm volatile("cp.async.wait_group 0;" ::: "memory");
        }
        __syncthreads();

        const char* Ah = sm + buf * BUFB;
        const char* Al = Ah + MATB;
        const char* Wh = Al + MATB;
        const char* Wl = Wh + MATB;

#pragma unroll
        for (int k0 = 0; k0 < 64; k0 += 16) {
            uint32_t ah[2][4], al[2][4], bh[8][2], bl[8][2];
#pragma unroll
            for (int m = 0; m < 2; m++) {
                int row = mwarp + m * 16 + tr;
                ah[m][0] = ldsb64(Ah, row,     k0 + tc * 2);
                ah[m][1] = ldsb64(Ah, row + 8, k0 + tc * 2);
                ah[m][2] = ldsb64(Ah, row,     k0 + tc * 2 + 8);
                ah[m][3] = ldsb64(Ah, row + 8, k0 + tc * 2 + 8);
                al[m][0] = ldsb64(Al, row,     k0 + tc * 2);
                al[m][1] = ldsb64(Al, row + 8, k0 + tc * 2);
                al[m][2] = ldsb64(Al, row,     k0 + tc * 2 + 8);
                al[m][3] = ldsb64(Al, row + 8, k0 + tc * 2 + 8);
            }
#pragma unroll
            for (int n = 0; n < 8; n++) {
                int wr = nwarp + n * 8 + tr;
                bh[n][0] = ldsb64(Wh, wr, k0 + tc * 2);
                bh[n][1] = ldsb64(Wh, wr, k0 + tc * 2 + 8);
                bl[n][0] = ldsb64(Wl, wr, k0 + tc * 2);
                bl[n][1] = ldsb64(Wl, wr, k0 + tc * 2 + 8);
            }
#pragma unroll
            for (int m = 0; m < 2; m++)
#pragma unroll
                for (int n = 0; n < 8; n++) {
                    mma16816(acc[m][n], ah[m], bh[n]);   // hi*hi
                    mma16816(acc[m][n], ah[m], bl[n]);   // hi*lo
                    mma16816(acc[m][n], al[m], bh[n]);   // lo*hi
                }
        }
        __syncthreads();   // buffer reuse guard
    }

    // epilogue: bias + relu (+ optional bf16 split write)
#pragma unroll
    for (int m = 0; m < 2; m++) {
#pragma unroll
        for (int half = 0; half < 2; half++) {
            int row = n0 + mwarp + m * 16 + half * 8 + tr;
            if (row < N_NODES) {
#pragma unroll
                for (int n = 0; n < 8; n++) {
                    int c = nwarp + n * 8 + tc * 2;
                    float v0 = fmaxf(acc[m][n][half * 2 + 0] + bias[c], 0.f);
                    float v1 = fmaxf(acc[m][n][half * 2 + 1] + bias[c + 1], 0.f);
                    *(float2*)(outf + (size_t)row * 128 + c) = make_float2(v0, v1);
                    if (write_split) {
                        __nv_bfloat16 h0, l0, h1b, l1b;
                        split1(v0, h0, l0);
                        split1(v1, h1b, l1b);
                        *(uint32_t*)(ohi + (size_t)row * 128 + c) = pack2(h0, h1b);
                        *(uint32_t*)(olo + (size_t)row * 128 + c) = pack2(l0, l1b);
                    }
                }
            }
        }
    }
}

// ---------------- pool (2-stage, deterministic) + final linear ----------------
__device__ __forceinline__ int lbound32(const int* __restrict__ a, int n, int v) {
    int lo = 0, hi = n;
    while (lo < hi) {
        int mid = (lo + hi) >> 1;
        if (a[mid] < v) lo = mid + 1; else hi = mid;
    }
    return lo;
}
__global__ void k_pool(const int* __restrict__ batch) {
    int b = blockIdx.x, g = b >> 2, q = b & 3, c = threadIdx.x;
    int s = lbound32(batch, N_NODES, g);
    int e = lbound32(batch, N_NODES, g + 1);
    float sum = 0.f;
    for (int n = s + q; n < e; n += 4) sum += g_h2[(size_t)n * 128 + c];
    g_psum[q][g][c] = sum;
    if (q == 0 && c == 0) g_cnt[g] = e - s;
}
__global__ void k_final(const float* __restrict__ Wlin, const float* __restrict__ blin,
                        float* __restrict__ out) {
    __shared__ float pooled[128];
    int g = blockIdx.x, t = threadIdx.x;
    float v = g_psum[0][g][t] + g_psum[1][g][t] + g_psum[2][g][t] + g_psum[3][g][t];
    pooled[t] = v / (float)max(g_cnt[g], 1);
    __syncthreads();
    if (t < 32) {
        float s = 0.f;
#pragma unroll 8
        for (int k = 0; k < 128; k++)
            s += pooled[k] * Wlin[t * 128 + k];
        out[g * 32 + t] = s + blin[t];
    }
}

// ---------------- launch ----------------
extern "C" void kernel_launch(void* const* d_in, const int* in_sizes, int n_in,
                              void* d_out, int out_size) {
    const float* x     = (const float*)d_in[0];
    const int*   ei    = (const int*)d_in[1];
    const int*   batch = (const int*)d_in[2];
    const float* W1l  = (const float*)d_in[3];
    const float* b1   = (const float*)d_in[4];
    const float* W1r  = (const float*)d_in[5];
    const float* W2l  = (const float*)d_in[6];
    const float* b2   = (const float*)d_in[7];
    const float* W2r  = (const float*)d_in[8];
    const float* Wlin = (const float*)d_in[9];
    const float* blin = (const float*)d_in[10];
    float* out = (float*)d_out;

    void *p;
    cudaGetSymbolAddress(&p, g_xhi);  __nv_bfloat16* xhi = (__nv_bfloat16*)p;
    cudaGetSymbolAddress(&p, g_xlo);  __nv_bfloat16* xlo = (__nv_bfloat16*)p;
    cudaGetSymbolAddress(&p, g_mhi);  __nv_bfloat16* mhi = (__nv_bfloat16*)p;
    cudaGetSymbolAddress(&p, g_mlo);  __nv_bfloat16* mlo = (__nv_bfloat16*)p;
    cudaGetSymbolAddress(&p, g_h1hi); __nv_bfloat16* h1hi = (__nv_bfloat16*)p;
    cudaGetSymbolAddress(&p, g_h1lo); __nv_bfloat16* h1lo = (__nv_bfloat16*)p;
    cudaGetSymbolAddress(&p, g_whi);  __nv_bfloat16* whi = (__nv_bfloat16*)p;
    cudaGetSymbolAddress(&p, g_wlo);  __nv_bfloat16* wlo = (__nv_bfloat16*)p;
    cudaGetSymbolAddress(&p, g_h1);   float* h1 = (float*)p;
    cudaGetSymbolAddress(&p, g_h2);   float* h2 = (float*)p;

    cudaFuncSetAttribute(k_tgemm, cudaFuncAttributeMaxDynamicSharedMemorySize, SMEM_GEMM);

    const int GEMM_GRID = NP / 128;       // 391
    const int AGG_GRID = NP / 8;          // warp per node, 256 thr/block

    // CSR build
    k_zero<<<(N_NODES + 255) / 256, 256>>>();
    k_hist_splitw<<<EB + 64, 256>>>(ei, W1l, W1r, W2l, W2r);
    k_scan1<<<SCAN_NB, SCAN_BS>>>();
    k_scan2<<<1, 128>>>();
    k_scan3<<<SCAN_NB, SCAN_BS>>>();
    k_fill<<<EB, 256>>>(ei);

    // layer 1 (agg fused with x split)
    k_agg<<<AGG_GRID, 256>>>(x, mhi, mlo, xhi, xlo);
    k_tgemm<<<GEMM_GRID, 256, SMEM_GEMM>>>(mhi, mlo, xhi, xlo,
                                           whi + 0, wlo + 0, whi + 16384, wlo + 16384,
                                           b1, h1, h1hi, h1lo, 1);
    // layer 2
    k_agg<<<AGG_GRID, 256>>>(h1, mhi, mlo, (__nv_bfloat16*)0, (__nv_bfloat16*)0);
    k_tgemm<<<GEMM_GRID, 256, SMEM_GEMM>>>(mhi, mlo, h1hi, h1lo,
                                           whi + 32768, wlo + 32768, whi + 49152, wlo + 49152,
                                           b2, h2, h1hi, h1lo, 0);

    // pool + final linear
    k_pool<<<N_GRAPHS * 4, 128>>>(batch);
    k_final<<<N_GRAPHS, 128>>>(Wlin, blin, out);
}